// round 1
// baseline (speedup 1.0000x reference)
#include <cuda_runtime.h>
#include <cuda_fp16.h>
#include <cstdint>
#include <cstddef>

#define INNER 31999
#define VOCAB 32000
#define DEPTH 18
#define NROWS 64      // B*T
#define KDIM  512
#define KC    32      // K chunk
#define NT    64      // nodes per block
#define SST   36      // smem row stride in floats (pad: conflict-free frags, 16B-aligned rows: 36*4=144=9*16)

// Log-prob table: [2*node + side][row], fp16. side 0 = log sigma(h), side 1 = log(1-sigma(h)).
__device__ __half g_L[(size_t)2 * INNER * NROWS];

__device__ __forceinline__ uint32_t smem_u32(const void* p) {
    return (uint32_t)__cvta_generic_to_shared(p);
}
__device__ __forceinline__ void cp_async16(uint32_t dst, const void* src, int srcBytes) {
    asm volatile("cp.async.cg.shared.global [%0], [%1], 16, %2;" :: "r"(dst), "l"(src), "r"(srcBytes));
}
__device__ __forceinline__ void cp_commit() { asm volatile("cp.async.commit_group;"); }
template<int N> __device__ __forceinline__ void cp_wait() { asm volatile("cp.async.wait_group %0;" :: "n"(N)); }

// ---------------------------------------------------------------------------
// Kernel 1: C[64, INNER] = att[64,512] @ W[INNER,512]^T via tf32 mma.sync,
// fused softplus epilogue -> fp16 L table.
// Block: 256 threads (8 warps: 4 M-warps x 2 N-warps). Block tile M=64, N=64.
// ---------------------------------------------------------------------------
__global__ __launch_bounds__(256, 4) void hs_gemm_kernel(
    const float* __restrict__ att, const float* __restrict__ W)
{
    __shared__ float As[2][NROWS * SST];
    __shared__ float Bs[2][NT * SST];

    const int tid  = threadIdx.x;
    const int nbase = blockIdx.x * NT;
    const int lane = tid & 31;
    const int warp = tid >> 5;
    const int gid  = lane >> 2;   // groupID
    const int tig  = lane & 3;    // threadID_in_group
    const int mb   = (warp & 3) * 16;   // warp M offset
    const int nb   = (warp >> 2) * 32;  // warp N offset (within block tile)

    float acc[4][4];
#pragma unroll
    for (int f = 0; f < 4; f++)
#pragma unroll
        for (int c = 0; c < 4; c++) acc[f][c] = 0.0f;

    auto load_chunk = [&](int c, int buf) {
#pragma unroll
        for (int i = 0; i < 2; i++) {
            int lin = tid + i * 256;        // 0..511 (64 rows x 8 float4)
            int row = lin >> 3;
            int k4  = (lin & 7) << 2;
            int kg  = c * KC + k4;
            cp_async16(smem_u32(&As[buf][row * SST + k4]), att + row * KDIM + kg, 16);
            int  wr = nbase + row;
            bool v  = (wr < INNER);
            cp_async16(smem_u32(&Bs[buf][row * SST + k4]),
                       W + (size_t)(v ? wr : 0) * KDIM + kg, v ? 16 : 0);
        }
        cp_commit();
    };

    const int NCHUNK = KDIM / KC; // 16
    load_chunk(0, 0);

    for (int c = 0; c < NCHUNK; c++) {
        if (c + 1 < NCHUNK) { load_chunk(c + 1, (c + 1) & 1); cp_wait<1>(); }
        else                { cp_wait<0>(); }
        __syncthreads();

        const float* A = As[c & 1];
        const float* B = Bs[c & 1];
#pragma unroll
        for (int kk = 0; kk < KC / 8; kk++) {
            const int k0 = kk * 8;
            uint32_t a0 = __float_as_uint(A[(mb + gid)     * SST + k0 + tig]);
            uint32_t a1 = __float_as_uint(A[(mb + gid + 8) * SST + k0 + tig]);
            uint32_t a2 = __float_as_uint(A[(mb + gid)     * SST + k0 + tig + 4]);
            uint32_t a3 = __float_as_uint(A[(mb + gid + 8) * SST + k0 + tig + 4]);
#pragma unroll
            for (int f = 0; f < 4; f++) {
                const int n8 = nb + f * 8;
                uint32_t b0 = __float_as_uint(B[(n8 + gid) * SST + k0 + tig]);
                uint32_t b1 = __float_as_uint(B[(n8 + gid) * SST + k0 + tig + 4]);
                asm volatile(
                    "mma.sync.aligned.m16n8k8.row.col.f32.tf32.tf32.f32 "
                    "{%0,%1,%2,%3}, {%4,%5,%6,%7}, {%8,%9}, {%0,%1,%2,%3};"
                    : "+f"(acc[f][0]), "+f"(acc[f][1]), "+f"(acc[f][2]), "+f"(acc[f][3])
                    : "r"(a0), "r"(a1), "r"(a2), "r"(a3), "r"(b0), "r"(b1));
            }
        }
        __syncthreads();
    }

    // Epilogue: h -> (log sigma(h), log(1-sigma(h))) via one softplus; clamp to log(1e-9).
#pragma unroll
    for (int f = 0; f < 4; f++) {
#pragma unroll
        for (int c = 0; c < 4; c++) {
            int m = mb + gid + ((c & 2) << 2);                    // +8 for c in {2,3}
            int n = nbase + nb + f * 8 + tig * 2 + (c & 1);
            if (n < INNER) {
                float h  = acc[f][c];
                float l  = __logf(1.0f + __expf(-fabsf(h)));      // log1p(e^{-|h|})
                float lp = fminf(h, 0.0f) - l;                    // log sigma(h)
                float ln = -fmaxf(h, 0.0f) - l;                   // log (1 - sigma(h))
                lp = fmaxf(lp, -20.7232658f);                     // log(1e-9) clip
                ln = fmaxf(ln, -20.7232658f);
                g_L[(size_t)(2 * n)     * NROWS + m] = __float2half_rn(lp);
                g_L[(size_t)(2 * n + 1) * NROWS + m] = __float2half_rn(ln);
            }
        }
    }
}

// ---------------------------------------------------------------------------
// Kernel 2: per vocab word, sum 18 path log-probs over all 64 rows.
// One warp per word (lane carries a row pair as half2). smem transpose for
// coalesced 32B-sector output writes.
// ---------------------------------------------------------------------------
__global__ __launch_bounds__(256) void hs_gather_kernel(
    const int* __restrict__ pidx, const float* __restrict__ psign,
    float* __restrict__ out)
{
    __shared__ float tr[NROWS * 9];   // [row][word-in-block], pad 9 vs bank conflicts

    const int tid  = threadIdx.x;
    const int lane = tid & 31;
    const int wl   = tid >> 5;                 // word within block (0..7)
    const int w    = blockIdx.x * 8 + wl;

    const __half2* Lp = reinterpret_cast<const __half2*>(g_L);
    float ax = 0.0f, ay = 0.0f;
#pragma unroll
    for (int d = 0; d < DEPTH; d++) {
        int j  = w * DEPTH + d;
        int ci = 2 * pidx[j] + (psign[j] < 0.0f ? 1 : 0);
        float2 v = __half22float2(Lp[(size_t)ci * 32 + lane]);  // rows 2*lane, 2*lane+1
        ax += v.x; ay += v.y;
    }
    tr[(2 * lane)     * 9 + wl] = ax;
    tr[(2 * lane + 1) * 9 + wl] = ay;
    __syncthreads();

    int row = tid >> 2;
    int wo  = (tid & 3) << 1;
    float2 o = make_float2(tr[row * 9 + wo], tr[row * 9 + wo + 1]);
    *reinterpret_cast<float2*>(out + (size_t)row * VOCAB + blockIdx.x * 8 + wo) = o;
}

extern "C" void kernel_launch(void* const* d_in, const int* in_sizes, int n_in,
                              void* d_out, int out_size)
{
    (void)in_sizes; (void)n_in; (void)out_size;
    const float* att   = (const float*)d_in[0];
    const float* W     = (const float*)d_in[1];
    const int*   pidx  = (const int*)d_in[2];
    const float* psign = (const float*)d_in[3];
    float* out = (float*)d_out;

    hs_gemm_kernel<<<(INNER + NT - 1) / NT, 256>>>(att, W);
    hs_gather_kernel<<<VOCAB / 8, 256>>>(pidx, psign, out);
}

// round 3
// speedup vs baseline: 1.4557x; 1.4557x over previous
#include <cuda_runtime.h>
#include <cuda_fp16.h>
#include <cstdint>
#include <cstddef>

#define INNER 31999
#define VOCAB 32000
#define DEPTH 18
#define NROWS 64          // B*T
#define KDIM  512
#define MT    128         // nodes per block tile
#define NCHUNK 16         // K chunks of 32 floats (128B per row per chunk)
#define NSTAGE 4
#define A_STAGE_BYTES 16384      // 128 rows * 128B
#define B_STAGE_BYTES 8192       // 64 rows * 128B
#define STAGE_BYTES   (A_STAGE_BYTES + B_STAGE_BYTES)   // 24576
#define SMEM_TOTAL    (NSTAGE * STAGE_BYTES)            // 98304

// Log-prob table: [2*node + side][row], fp16. side 0 = log sigma, side 1 = log(1-sigma).
// Padded to VOCAB nodes so the last block (node 31999 = dummy) can store safely.
__device__ __half g_L[(size_t)2 * VOCAB * NROWS];

// ---------------- helpers ----------------
__device__ __forceinline__ uint32_t smem_u32(const void* p) {
    return (uint32_t)__cvta_generic_to_shared(p);
}
__device__ __forceinline__ void cp_async16(uint32_t dst, const void* src, int srcBytes) {
    asm volatile("cp.async.cg.shared.global [%0], [%1], 16, %2;" :: "r"(dst), "l"(src), "r"(srcBytes));
}
__device__ __forceinline__ void cp_commit() { asm volatile("cp.async.commit_group;"); }
template<int N> __device__ __forceinline__ void cp_wait() { asm volatile("cp.async.wait_group %0;" :: "n"(N)); }

__device__ __forceinline__ void ldsm4(uint32_t& r0, uint32_t& r1, uint32_t& r2, uint32_t& r3,
                                      uint32_t addr) {
    asm volatile("ldmatrix.sync.aligned.m8n8.x4.shared.b16 {%0,%1,%2,%3}, [%4];"
                 : "=r"(r0), "=r"(r1), "=r"(r2), "=r"(r3) : "r"(addr));
}
__device__ __forceinline__ void mma_tf32(float* c, uint32_t a0, uint32_t a1, uint32_t a2, uint32_t a3,
                                         uint32_t b0, uint32_t b1) {
    asm volatile(
        "mma.sync.aligned.m16n8k8.row.col.f32.tf32.tf32.f32 "
        "{%0,%1,%2,%3}, {%4,%5,%6,%7}, {%8,%9}, {%0,%1,%2,%3};"
        : "+f"(c[0]), "+f"(c[1]), "+f"(c[2]), "+f"(c[3])
        : "r"(a0), "r"(a1), "r"(a2), "r"(a3), "r"(b0), "r"(b1));
}

// ---------------------------------------------------------------------------
// Kernel 1: C[128 nodes, 64 rows] per block = W_tile @ att^T, tf32 mma.sync,
// ldmatrix fragment loads, 4-stage cp.async pipeline, softplus epilogue with
// smem-transposed vectorized stores into fp16 g_L.
// 128 threads (4 warps), warp tile 32(M) x 64(N).
// ---------------------------------------------------------------------------
__global__ __launch_bounds__(128, 2) void hs_gemm_kernel(
    const float* __restrict__ att, const float* __restrict__ W)
{
    extern __shared__ char smem[];
    const uint32_t sb = smem_u32(smem);

    const int tid   = threadIdx.x;
    const int lane  = tid & 31;
    const int warp  = tid >> 5;
    const int nbase = blockIdx.x * MT;
    const int gid   = lane >> 2;
    const int tig   = lane & 3;

    // -------- stage loader (SW128 swizzle: 16B chunk c of row r -> c16 ^ (r&7)) --------
    auto load_stage = [&](int t) {
        const uint32_t base = sb + (uint32_t)(t & (NSTAGE - 1)) * STAGE_BYTES;
#pragma unroll
        for (int i = 0; i < 8; i++) {                  // A: 128 rows x 8 chunks
            int id  = tid + i * 128;
            int row = id >> 3;
            int c16 = id & 7;
            uint32_t dst = base + (uint32_t)(row * 128 + ((c16 * 16) ^ ((row & 7) << 4)));
            int  wr = nbase + row;
            bool v  = (wr < INNER);
            cp_async16(dst, W + (size_t)(v ? wr : 0) * KDIM + t * 32 + c16 * 4, v ? 16 : 0);
        }
#pragma unroll
        for (int i = 0; i < 4; i++) {                  // B: 64 rows x 8 chunks
            int id  = tid + i * 128;
            int row = id >> 3;
            int c16 = id & 7;
            uint32_t dst = base + A_STAGE_BYTES
                         + (uint32_t)(row * 128 + ((c16 * 16) ^ ((row & 7) << 4)));
            cp_async16(dst, att + (size_t)row * KDIM + t * 32 + c16 * 4, 16);
        }
        cp_commit();
    };

    // -------- ldmatrix per-lane address precompute --------
    const int li = lane >> 3;   // matrix index 0..3
    const int lr = lane & 7;    // row within matrix
    // A (x4 covers one m16k8 tile): mats = {m0 k0-3, m0+8 k0-3, m0 k4-7, m0+8 k4-7}
    uint32_t aBase[2], aSwz[2];
#pragma unroll
    for (int mt = 0; mt < 2; mt++) {
        int row = warp * 32 + mt * 16 + lr + ((li & 1) << 3);
        aBase[mt] = (uint32_t)(row * 128);
        aSwz[mt]  = (uint32_t)(((li >> 1) << 4) ^ ((row & 7) << 4));
    }
    // B (x4 covers two n8k8 tiles): mats = {n0 k0-3, n0 k4-7, n0+8 k0-3, n0+8 k4-7}
    uint32_t bBase[4], bSwz[4];
#pragma unroll
    for (int q = 0; q < 4; q++) {
        int row = q * 16 + lr + ((li >> 1) << 3);
        bBase[q] = (uint32_t)(row * 128);
        bSwz[q]  = (uint32_t)(((li & 1) << 4) ^ ((row & 7) << 4));
    }

    float acc[2][8][4];
#pragma unroll
    for (int mt = 0; mt < 2; mt++)
#pragma unroll
        for (int f = 0; f < 8; f++)
#pragma unroll
            for (int c = 0; c < 4; c++) acc[mt][f][c] = 0.0f;

    load_stage(0); load_stage(1); load_stage(2);

    for (int t = 0; t < NCHUNK; t++) {
        cp_wait<2>();
        __syncthreads();
        // prefetch next stage first (overlaps with compute below)
        if (t + 3 < NCHUNK) load_stage(t + 3); else cp_commit();

        const uint32_t Ab = sb + (uint32_t)(t & (NSTAGE - 1)) * STAGE_BYTES;
        const uint32_t Bb = Ab + A_STAGE_BYTES;
#pragma unroll
        for (int kk = 0; kk < 4; kk++) {
            const uint32_t k32 = (uint32_t)(kk * 32);
            uint32_t a[2][4];
#pragma unroll
            for (int mt = 0; mt < 2; mt++)
                ldsm4(a[mt][0], a[mt][1], a[mt][2], a[mt][3],
                      Ab + aBase[mt] + (k32 ^ aSwz[mt]));
            uint32_t b[8][2];
#pragma unroll
            for (int q = 0; q < 4; q++) {
                uint32_t r0, r1, r2, r3;
                ldsm4(r0, r1, r2, r3, Bb + bBase[q] + (k32 ^ bSwz[q]));
                b[q * 2][0] = r0; b[q * 2][1] = r1;
                b[q * 2 + 1][0] = r2; b[q * 2 + 1][1] = r3;
            }
#pragma unroll
            for (int mt = 0; mt < 2; mt++)
#pragma unroll
                for (int f = 0; f < 8; f++)
                    mma_tf32(acc[mt][f], a[mt][0], a[mt][1], a[mt][2], a[mt][3],
                             b[f][0], b[f][1]);
        }
    }
    cp_wait<0>();
    __syncthreads();   // everyone done computing before smem reuse

    // -------- epilogue: softplus -> fp16, smem transpose (swizzled), flat copy --------
    // smem rows s = 2*node_local + side (256 rows x 128B = 32KB); swizzle by node&7.
#pragma unroll
    for (int mt = 0; mt < 2; mt++) {
#pragma unroll
        for (int m8 = 0; m8 < 2; m8++) {
            const int nl = warp * 32 + mt * 16 + m8 * 8 + gid;   // local node 0..127
            const uint32_t swz = (uint32_t)((nl & 7) << 4);
#pragma unroll
            for (int f = 0; f < 8; f++) {
                float lp[2], ln[2];
#pragma unroll
                for (int u = 0; u < 2; u++) {
                    float h = acc[mt][f][m8 * 2 + u];
                    float l = __logf(1.0f + __expf(-fabsf(h)));
                    lp[u] = fmaxf(fminf(h, 0.0f) - l, -20.7232658f);   // log sigma
                    ln[u] = fmaxf(-fmaxf(h, 0.0f) - l, -20.7232658f);  // log(1-sigma)
                }
                const uint32_t col = (uint32_t)(f * 16 + tig * 4) ^ swz;
                *reinterpret_cast<__half2*>(smem + (2 * nl)     * 128 + col) = __floats2half2_rn(lp[0], lp[1]);
                *reinterpret_cast<__half2*>(smem + (2 * nl + 1) * 128 + col) = __floats2half2_rn(ln[0], ln[1]);
            }
        }
    }
    __syncthreads();

    char* gdst = reinterpret_cast<char*>(&g_L[(size_t)(2 * nbase) * NROWS]);
#pragma unroll
    for (int i = 0; i < 16; i++) {
        int u = tid + i * 128;               // 16B unit, 0..2047
        int s = u >> 3, j = u & 7;
        uint32_t soff = (uint32_t)(s * 128 + ((j ^ ((s >> 1) & 7)) << 4));
        uint4 v = *reinterpret_cast<const uint4*>(smem + soff);
        *reinterpret_cast<uint4*>(gdst + (size_t)u * 16) = v;
    }
}

// ---------------------------------------------------------------------------
// Kernel 2: per vocab word, sum 18 path log-probs over all 64 rows.
// One warp per word; path indices loaded once by lanes 0..17, broadcast via shfl.
// ---------------------------------------------------------------------------
__global__ __launch_bounds__(256) void hs_gather_kernel(
    const int* __restrict__ pidx, const float* __restrict__ psign,
    float* __restrict__ out)
{
    __shared__ float tr[NROWS * 9];   // [row][word-in-block], pad 9 vs bank conflicts

    const int tid  = threadIdx.x;
    const int lane = tid & 31;
    const int wl   = tid >> 5;                 // word within block (0..7)
    const int w    = blockIdx.x * 8 + wl;

    int myci = 0;
    if (lane < DEPTH) {
        int j = w * DEPTH + lane;
        myci  = 2 * pidx[j] + (psign[j] < 0.0f ? 1 : 0);
    }

    const __half2* Lp = reinterpret_cast<const __half2*>(g_L);
    float ax = 0.0f, ay = 0.0f;
#pragma unroll
    for (int d = 0; d < DEPTH; d++) {
        int ci = __shfl_sync(0xffffffffu, myci, d);
        float2 v = __half22float2(__ldg(&Lp[(size_t)ci * 32 + lane]));  // rows 2*lane, 2*lane+1
        ax += v.x; ay += v.y;
    }
    tr[(2 * lane)     * 9 + wl] = ax;
    tr[(2 * lane + 1) * 9 + wl] = ay;
    __syncthreads();

    int row = tid >> 2;
    int wo  = (tid & 3) << 1;
    float2 o = make_float2(tr[row * 9 + wo], tr[row * 9 + wo + 1]);
    *reinterpret_cast<float2*>(out + (size_t)row * VOCAB + blockIdx.x * 8 + wo) = o;
}

extern "C" void kernel_launch(void* const* d_in, const int* in_sizes, int n_in,
                              void* d_out, int out_size)
{
    (void)in_sizes; (void)n_in; (void)out_size;
    const float* att   = (const float*)d_in[0];
    const float* W     = (const float*)d_in[1];
    const int*   pidx  = (const int*)d_in[2];
    const float* psign = (const float*)d_in[3];
    float* out = (float*)d_out;

    cudaFuncSetAttribute(hs_gemm_kernel, cudaFuncAttributeMaxDynamicSharedMemorySize, SMEM_TOTAL);
    hs_gemm_kernel<<<(INNER + MT - 1) / MT, 128, SMEM_TOTAL>>>(att, W);
    hs_gather_kernel<<<VOCAB / 8, 256>>>(pidx, psign, out);
}

// round 4
// speedup vs baseline: 1.4587x; 1.0020x over previous
#include <cuda_runtime.h>
#include <cuda_fp16.h>
#include <cstdint>
#include <cstddef>

#define INNER 31999
#define VOCAB 32000
#define DEPTH 18
#define NROWS 64          // B*T
#define KDIM  512
#define MT    128         // nodes per block tile
#define NCHUNK 16         // K chunks of 32 floats (128B per row per chunk)
#define NSTAGE 4
#define A_STAGE_BYTES 16384      // 128 rows * 128B
#define B_STAGE_BYTES 8192       // 64 rows * 128B
#define STAGE_BYTES   (A_STAGE_BYTES + B_STAGE_BYTES)   // 24576
#define SMEM_TOTAL    (NSTAGE * STAGE_BYTES)            // 98304

// Log-prob table: [2*node + side][row], fp16. side 0 = log sigma, side 1 = log(1-sigma).
// Padded to VOCAB nodes so the last block (node 31999 = dummy) can store safely.
__device__ __half g_L[(size_t)2 * VOCAB * NROWS];

// ---------------- helpers ----------------
__device__ __forceinline__ uint32_t smem_u32(const void* p) {
    return (uint32_t)__cvta_generic_to_shared(p);
}
__device__ __forceinline__ void cp_async16(uint32_t dst, const void* src, int srcBytes) {
    asm volatile("cp.async.cg.shared.global [%0], [%1], 16, %2;" :: "r"(dst), "l"(src), "r"(srcBytes));
}
__device__ __forceinline__ void cp_commit() { asm volatile("cp.async.commit_group;"); }
template<int N> __device__ __forceinline__ void cp_wait() { asm volatile("cp.async.wait_group %0;" :: "n"(N)); }

__device__ __forceinline__ void ldsm4(uint32_t& r0, uint32_t& r1, uint32_t& r2, uint32_t& r3,
                                      uint32_t addr) {
    asm volatile("ldmatrix.sync.aligned.m8n8.x4.shared.b16 {%0,%1,%2,%3}, [%4];"
                 : "=r"(r0), "=r"(r1), "=r"(r2), "=r"(r3) : "r"(addr));
}
__device__ __forceinline__ void mma_tf32(float* c, uint32_t a0, uint32_t a1, uint32_t a2, uint32_t a3,
                                         uint32_t b0, uint32_t b1) {
    asm volatile(
        "mma.sync.aligned.m16n8k8.row.col.f32.tf32.tf32.f32 "
        "{%0,%1,%2,%3}, {%4,%5,%6,%7}, {%8,%9}, {%0,%1,%2,%3};"
        : "+f"(c[0]), "+f"(c[1]), "+f"(c[2]), "+f"(c[3])
        : "r"(a0), "r"(a1), "r"(a2), "r"(a3), "r"(b0), "r"(b1));
}

// ---------------------------------------------------------------------------
// Kernel 1: C[128 nodes, 64 rows] per block = W_tile @ att^T, tf32 mma.sync.
// 256 threads (8 warps: 4 M x 2 N), warp tile 32(M) x 32(N).
// ldmatrix fragment loads, 4-stage cp.async pipeline, softplus epilogue with
// smem-transposed vectorized stores into fp16 g_L.
// ---------------------------------------------------------------------------
__global__ __launch_bounds__(256, 2) void hs_gemm_kernel(
    const float* __restrict__ att, const float* __restrict__ W)
{
    extern __shared__ char smem[];
    const uint32_t sb = smem_u32(smem);

    const int tid   = threadIdx.x;
    const int lane  = tid & 31;
    const int warp  = tid >> 5;
    const int wm    = warp & 3;        // warp M index (rows wm*32..+31)
    const int wn    = warp >> 2;       // warp N index (cols wn*32..+31)
    const int nbase = blockIdx.x * MT;
    const int gid   = lane >> 2;
    const int tig   = lane & 3;

    // -------- stage loader (SW128 swizzle: 16B chunk c of row r -> c ^ (r&7)) --------
    auto load_stage = [&](int t) {
        const uint32_t base = sb + (uint32_t)(t & (NSTAGE - 1)) * STAGE_BYTES;
#pragma unroll
        for (int i = 0; i < 4; i++) {                  // A: 128 rows x 8 chunks = 1024
            int id  = tid + i * 256;
            int row = id >> 3;
            int c16 = id & 7;
            uint32_t dst = base + (uint32_t)(row * 128 + ((c16 * 16) ^ ((row & 7) << 4)));
            int  wr = nbase + row;
            bool v  = (wr < INNER);
            cp_async16(dst, W + (size_t)(v ? wr : 0) * KDIM + t * 32 + c16 * 4, v ? 16 : 0);
        }
#pragma unroll
        for (int i = 0; i < 2; i++) {                  // B: 64 rows x 8 chunks = 512
            int id  = tid + i * 256;
            int row = id >> 3;
            int c16 = id & 7;
            uint32_t dst = base + A_STAGE_BYTES
                         + (uint32_t)(row * 128 + ((c16 * 16) ^ ((row & 7) << 4)));
            cp_async16(dst, att + (size_t)row * KDIM + t * 32 + c16 * 4, 16);
        }
        cp_commit();
    };

    // -------- ldmatrix per-lane address precompute --------
    const int li = lane >> 3;   // matrix index 0..3
    const int lr = lane & 7;    // row within matrix
    // A (x4 covers one m16k8 tile): mats = {m0 k0-3, m0+8 k0-3, m0 k4-7, m0+8 k4-7}
    uint32_t aBase[2], aSwz[2];
#pragma unroll
    for (int mt = 0; mt < 2; mt++) {
        int row = wm * 32 + mt * 16 + lr + ((li & 1) << 3);
        aBase[mt] = (uint32_t)(row * 128);
        aSwz[mt]  = (uint32_t)(((li >> 1) << 4) ^ ((row & 7) << 4));
    }
    // B (x4 covers two n8k8 tiles): mats = {n0 k0-3, n0 k4-7, n0+8 k0-3, n0+8 k4-7}
    uint32_t bBase[2], bSwz[2];
#pragma unroll
    for (int q = 0; q < 2; q++) {
        int row = wn * 32 + q * 16 + lr + ((li >> 1) << 3);
        bBase[q] = (uint32_t)(row * 128);
        bSwz[q]  = (uint32_t)(((li & 1) << 4) ^ ((row & 7) << 4));
    }

    float acc[2][4][4];
#pragma unroll
    for (int mt = 0; mt < 2; mt++)
#pragma unroll
        for (int f = 0; f < 4; f++)
#pragma unroll
            for (int c = 0; c < 4; c++) acc[mt][f][c] = 0.0f;

    load_stage(0); load_stage(1); load_stage(2);

    for (int t = 0; t < NCHUNK; t++) {
        cp_wait<2>();
        __syncthreads();
        // prefetch next stage first (overlaps with compute below)
        if (t + 3 < NCHUNK) load_stage(t + 3); else cp_commit();

        const uint32_t Ab = sb + (uint32_t)(t & (NSTAGE - 1)) * STAGE_BYTES;
        const uint32_t Bb = Ab + A_STAGE_BYTES;
#pragma unroll
        for (int kk = 0; kk < 4; kk++) {
            const uint32_t k32 = (uint32_t)(kk * 32);
            uint32_t a[2][4];
#pragma unroll
            for (int mt = 0; mt < 2; mt++)
                ldsm4(a[mt][0], a[mt][1], a[mt][2], a[mt][3],
                      Ab + aBase[mt] + (k32 ^ aSwz[mt]));
            uint32_t b[4][2];
#pragma unroll
            for (int q = 0; q < 2; q++) {
                uint32_t r0, r1, r2, r3;
                ldsm4(r0, r1, r2, r3, Bb + bBase[q] + (k32 ^ bSwz[q]));
                b[q * 2][0] = r0; b[q * 2][1] = r1;
                b[q * 2 + 1][0] = r2; b[q * 2 + 1][1] = r3;
            }
#pragma unroll
            for (int mt = 0; mt < 2; mt++)
#pragma unroll
                for (int f = 0; f < 4; f++)
                    mma_tf32(acc[mt][f], a[mt][0], a[mt][1], a[mt][2], a[mt][3],
                             b[f][0], b[f][1]);
        }
    }
    cp_wait<0>();
    __syncthreads();   // everyone done computing before smem reuse

    // -------- epilogue: softplus -> fp16, smem transpose (swizzled), flat copy --------
    // smem rows s = 2*node_local + side (256 rows x 128B = 32KB); swizzle by node&7.
#pragma unroll
    for (int mt = 0; mt < 2; mt++) {
#pragma unroll
        for (int m8 = 0; m8 < 2; m8++) {
            const int nl = wm * 32 + mt * 16 + m8 * 8 + gid;     // local node 0..127
            const uint32_t swz = (uint32_t)((nl & 7) << 4);
#pragma unroll
            for (int f = 0; f < 4; f++) {
                float lp[2], ln[2];
#pragma unroll
                for (int u = 0; u < 2; u++) {
                    float h = acc[mt][f][m8 * 2 + u];
                    float l = __logf(1.0f + __expf(-fabsf(h)));
                    lp[u] = fmaxf(fminf(h, 0.0f) - l, -20.7232658f);   // log sigma
                    ln[u] = fmaxf(-fmaxf(h, 0.0f) - l, -20.7232658f);  // log(1-sigma)
                }
                const uint32_t col = (uint32_t)(wn * 64 + f * 16 + tig * 4) ^ swz;
                *reinterpret_cast<__half2*>(smem + (2 * nl)     * 128 + col) = __floats2half2_rn(lp[0], lp[1]);
                *reinterpret_cast<__half2*>(smem + (2 * nl + 1) * 128 + col) = __floats2half2_rn(ln[0], ln[1]);
            }
        }
    }
    __syncthreads();

    char* gdst = reinterpret_cast<char*>(&g_L[(size_t)(2 * nbase) * NROWS]);
#pragma unroll
    for (int i = 0; i < 8; i++) {
        int u = tid + i * 256;               // 16B unit, 0..2047
        int s = u >> 3, j = u & 7;
        uint32_t soff = (uint32_t)(s * 128 + ((j ^ ((s >> 1) & 7)) << 4));
        uint4 v = *reinterpret_cast<const uint4*>(smem + soff);
        *reinterpret_cast<uint4*>(gdst + (size_t)u * 16) = v;
    }
}

// ---------------------------------------------------------------------------
// Kernel 2: per vocab word, sum 18 path log-probs over all 64 rows.
// One warp per word; indices broadcast via shfl; fp16 chunked accumulation
// (3 depths per HADD2 chunk, fp32 flush) to cut issue pressure.
// ---------------------------------------------------------------------------
__global__ __launch_bounds__(256) void hs_gather_kernel(
    const int* __restrict__ pidx, const float* __restrict__ psign,
    float* __restrict__ out)
{
    __shared__ float tr[NROWS * 9];   // [row][word-in-block], pad 9 vs bank conflicts

    const int tid  = threadIdx.x;
    const int lane = tid & 31;
    const int wl   = tid >> 5;                 // word within block (0..7)
    const int w    = blockIdx.x * 8 + wl;

    int myci = 0;
    if (lane < DEPTH) {
        int j = w * DEPTH + lane;
        myci  = 2 * pidx[j] + (psign[j] < 0.0f ? 1 : 0);
    }

    const __half2* Lp = reinterpret_cast<const __half2*>(g_L);
    float ax = 0.0f, ay = 0.0f;
#pragma unroll
    for (int g = 0; g < 6; g++) {
        __half2 hacc = __float2half2_rn(0.0f);
#pragma unroll
        for (int dd = 0; dd < 3; dd++) {
            int ci = __shfl_sync(0xffffffffu, myci, g * 3 + dd);
            hacc = __hadd2(hacc, __ldg(&Lp[(size_t)ci * 32 + lane]));  // rows 2*lane, 2*lane+1
        }
        float2 v = __half22float2(hacc);
        ax += v.x; ay += v.y;
    }
    tr[(2 * lane)     * 9 + wl] = ax;
    tr[(2 * lane + 1) * 9 + wl] = ay;
    __syncthreads();

    int row = tid >> 2;
    int wo  = (tid & 3) << 1;
    float2 o = make_float2(tr[row * 9 + wo], tr[row * 9 + wo + 1]);
    *reinterpret_cast<float2*>(out + (size_t)row * VOCAB + blockIdx.x * 8 + wo) = o;
}

extern "C" void kernel_launch(void* const* d_in, const int* in_sizes, int n_in,
                              void* d_out, int out_size)
{
    (void)in_sizes; (void)n_in; (void)out_size;
    const float* att   = (const float*)d_in[0];
    const float* W     = (const float*)d_in[1];
    const int*   pidx  = (const int*)d_in[2];
    const float* psign = (const float*)d_in[3];
    float* out = (float*)d_out;

    cudaFuncSetAttribute(hs_gemm_kernel, cudaFuncAttributeMaxDynamicSharedMemorySize, SMEM_TOTAL);
    hs_gemm_kernel<<<(INNER + MT - 1) / MT, 256, SMEM_TOTAL>>>(att, W);
    hs_gather_kernel<<<VOCAB / 8, 256>>>(pidx, psign, out);
}

// round 6
// speedup vs baseline: 1.4722x; 1.0093x over previous
#include <cuda_runtime.h>
#include <cuda_fp16.h>
#include <cstdint>
#include <cstddef>

#define INNER 31999
#define VOCAB 32000
#define DEPTH 18
#define NROWS 64          // B*T
#define KDIM  512
#define MT    128         // nodes per block tile
#define KC    64          // fp16 K elems per chunk (=128B per row)
#define NCHUNK (KDIM / KC)       // 8
#define A_ST 16384               // 128 rows * 128B fp16
#define B_ST 8192                // 64 rows * 128B fp16
#define STB  (A_ST + B_ST)       // 24576
#define SMEM_TOTAL (2 * STB)     // 49152 (double buffer); epilogue reuses 32KB

// Log-prob table: [2*node + side][row], fp16. side 0 = log sigma, side 1 = log(1-sigma).
// Padded to VOCAB nodes so the tail block can store unconditionally.
__device__ __half g_L[(size_t)2 * VOCAB * NROWS];

// ---------------- helpers ----------------
__device__ __forceinline__ uint32_t smem_u32(const void* p) {
    return (uint32_t)__cvta_generic_to_shared(p);
}
__device__ __forceinline__ void ldsm4(uint32_t& r0, uint32_t& r1, uint32_t& r2, uint32_t& r3,
                                      uint32_t addr) {
    asm volatile("ldmatrix.sync.aligned.m8n8.x4.shared.b16 {%0,%1,%2,%3}, [%4];"
                 : "=r"(r0), "=r"(r1), "=r"(r2), "=r"(r3) : "r"(addr));
}
__device__ __forceinline__ void mma_f16(float* c, const uint32_t* a, const uint32_t* b) {
    asm volatile(
        "mma.sync.aligned.m16n8k16.row.col.f32.f16.f16.f32 "
        "{%0,%1,%2,%3}, {%4,%5,%6,%7}, {%8,%9}, {%0,%1,%2,%3};"
        : "+f"(c[0]), "+f"(c[1]), "+f"(c[2]), "+f"(c[3])
        : "r"(a[0]), "r"(a[1]), "r"(a[2]), "r"(a[3]), "r"(b[0]), "r"(b[1]));
}

// ---------------------------------------------------------------------------
// Kernel 1: C[128 nodes, 64 rows] per block = W_tile @ att^T.
// fp16 m16n8k16 mma (fp32 acc). Inputs converted fp32->fp16 in registers while
// staging; 2-stage smem ring + register LDG pipeline. 256 threads (8 warps,
// warp tile 32M x 32N). Softplus epilogue, smem transpose, vectorized g_L store.
// ---------------------------------------------------------------------------
__global__ __launch_bounds__(256, 2) void hs_gemm_kernel(
    const float* __restrict__ att, const float* __restrict__ W)
{
    extern __shared__ char smem[];
    const uint32_t sb = smem_u32(smem);

    const int tid   = threadIdx.x;
    const int lane  = tid & 31;
    const int warp  = tid >> 5;
    const int wm    = warp & 3;        // warp M index (rows wm*32..+31)
    const int wn    = warp >> 2;       // warp N index (cols wn*32..+31)
    const int nbase = blockIdx.x * MT;
    const int gid   = lane >> 2;
    const int tig   = lane & 3;

    // -------- register staging: LDG fp32 --------
    float4 ra[8], rb[4];
    auto ldg_stage = [&](int t) {
#pragma unroll
        for (int i = 0; i < 8; i++) {              // A: 128 rows x 16 float4 = 2048
            int u = tid + i * 256;
            int row = u >> 4, f4 = u & 15;
            int wr = nbase + row;
            if (wr < INNER)
                ra[i] = *reinterpret_cast<const float4*>(W + (size_t)wr * KDIM + t * KC + f4 * 4);
            else
                ra[i] = make_float4(0.f, 0.f, 0.f, 0.f);
        }
#pragma unroll
        for (int i = 0; i < 4; i++) {              // B: 64 rows x 16 float4 = 1024
            int u = tid + i * 256;
            int row = u >> 4, f4 = u & 15;
            rb[i] = *reinterpret_cast<const float4*>(att + (size_t)row * KDIM + t * KC + f4 * 4);
        }
    };
    // -------- convert + STS into swizzled fp16 stage --------
    auto sts_stage = [&](int buf) {
        const uint32_t base = sb + (uint32_t)buf * STB;
#pragma unroll
        for (int i = 0; i < 8; i++) {
            int u = tid + i * 256;
            int row = u >> 4, f4 = u & 15;
            uint32_t off = base + (uint32_t)(row * 128
                         + ((((uint32_t)(f4 >> 1) << 4) ^ ((row & 7) << 4)))
                         + (f4 & 1) * 8);
            __half2 p0 = __floats2half2_rn(ra[i].x, ra[i].y);
            __half2 p1 = __floats2half2_rn(ra[i].z, ra[i].w);
            asm volatile("st.shared.v2.b32 [%0], {%1, %2};"
                         :: "r"(off), "r"(*(uint32_t*)&p0), "r"(*(uint32_t*)&p1));
        }
#pragma unroll
        for (int i = 0; i < 4; i++) {
            int u = tid + i * 256;
            int row = u >> 4, f4 = u & 15;
            uint32_t off = base + A_ST + (uint32_t)(row * 128
                         + ((((uint32_t)(f4 >> 1) << 4) ^ ((row & 7) << 4)))
                         + (f4 & 1) * 8);
            __half2 p0 = __floats2half2_rn(rb[i].x, rb[i].y);
            __half2 p1 = __floats2half2_rn(rb[i].z, rb[i].w);
            asm volatile("st.shared.v2.b32 [%0], {%1, %2};"
                         :: "r"(off), "r"(*(uint32_t*)&p0), "r"(*(uint32_t*)&p1));
        }
    };

    // -------- ldmatrix per-lane address precompute --------
    const int li = lane >> 3;   // matrix index 0..3
    const int lr = lane & 7;    // row within matrix
    // A x4 = m16k16: row = m0 + lr + (li&1)*8, 16B-col = (li>>1) (k halves)
    uint32_t aOff[2], aXor[2];
#pragma unroll
    for (int mt = 0; mt < 2; mt++) {
        int row = wm * 32 + mt * 16 + lr + ((li & 1) << 3);
        aOff[mt] = (uint32_t)(row * 128);
        aXor[mt] = (uint32_t)((((uint32_t)(li >> 1)) << 4) ^ ((row & 7) << 4));
    }
    // B x4 = n16k16: row = n0 + lr + (li&1)*8, same col pattern
    uint32_t bOff[2], bXor[2];
#pragma unroll
    for (int q = 0; q < 2; q++) {
        int row = wn * 32 + q * 16 + lr + ((li & 1) << 3);
        bOff[q] = (uint32_t)(row * 128);
        bXor[q] = (uint32_t)((((uint32_t)(li >> 1)) << 4) ^ ((row & 7) << 4));
    }

    float acc[2][4][4];
#pragma unroll
    for (int mt = 0; mt < 2; mt++)
#pragma unroll
        for (int f = 0; f < 4; f++)
#pragma unroll
            for (int c = 0; c < 4; c++) acc[mt][f][c] = 0.0f;

    // -------- pipeline: regs hold stage t+1; smem buf[t&1] ready at loop top --------
    ldg_stage(0);
    sts_stage(0);
    ldg_stage(1);
    __syncthreads();

    for (int t = 0; t < NCHUNK; t++) {
        if (t + 1 < NCHUNK) sts_stage((t + 1) & 1);   // guarded by sync at end of t-1
        if (t + 2 < NCHUNK) ldg_stage(t + 2);         // in flight across compute

        const uint32_t Ab = sb + (uint32_t)(t & 1) * STB;
        const uint32_t Bb = Ab + A_ST;
#pragma unroll
        for (int ks = 0; ks < 4; ks++) {              // 4 x k16 per chunk
            const uint32_t kb = (uint32_t)(ks * 32);  // bytes
            uint32_t a[2][4];
#pragma unroll
            for (int mt = 0; mt < 2; mt++)
                ldsm4(a[mt][0], a[mt][1], a[mt][2], a[mt][3],
                      Ab + aOff[mt] + (kb ^ aXor[mt]));
            uint32_t b[4][2];
#pragma unroll
            for (int q = 0; q < 2; q++) {
                uint32_t r0, r1, r2, r3;
                ldsm4(r0, r1, r2, r3, Bb + bOff[q] + (kb ^ bXor[q]));
                b[q * 2][0] = r0;     b[q * 2][1] = r2;     // lower n8: b0=k0-7, b1=k8-15
                b[q * 2 + 1][0] = r1; b[q * 2 + 1][1] = r3; // upper n8
            }
#pragma unroll
            for (int mt = 0; mt < 2; mt++)
#pragma unroll
                for (int f = 0; f < 4; f++)
                    mma_f16(acc[mt][f], a[mt], b[f]);
        }
        __syncthreads();
    }

    // -------- epilogue: softplus -> fp16, smem transpose (swizzled), flat copy --------
#pragma unroll
    for (int mt = 0; mt < 2; mt++) {
#pragma unroll
        for (int m8 = 0; m8 < 2; m8++) {
            const int nl = wm * 32 + mt * 16 + m8 * 8 + gid;     // local node 0..127
            const uint32_t swz = (uint32_t)((nl & 7) << 4);
#pragma unroll
            for (int f = 0; f < 4; f++) {
                float lp[2], ln[2];
#pragma unroll
                for (int u = 0; u < 2; u++) {
                    float h = acc[mt][f][m8 * 2 + u];
                    float l = __logf(1.0f + __expf(-fabsf(h)));
                    lp[u] = fmaxf(fminf(h, 0.0f) - l, -20.7232658f);   // log sigma
                    ln[u] = fmaxf(-fmaxf(h, 0.0f) - l, -20.7232658f);  // log(1-sigma)
                }
                const uint32_t col = (uint32_t)(wn * 64 + f * 16 + tig * 4) ^ swz;
                *reinterpret_cast<__half2*>(smem + (2 * nl)     * 128 + col) = __floats2half2_rn(lp[0], lp[1]);
                *reinterpret_cast<__half2*>(smem + (2 * nl + 1) * 128 + col) = __floats2half2_rn(ln[0], ln[1]);
            }
        }
    }
    __syncthreads();

    char* gdst = reinterpret_cast<char*>(&g_L[(size_t)(2 * nbase) * NROWS]);
#pragma unroll
    for (int i = 0; i < 8; i++) {
        int u = tid + i * 256;               // 16B unit, 0..2047
        int s = u >> 3, j = u & 7;
        uint32_t soff = (uint32_t)(s * 128 + ((j ^ ((s >> 1) & 7)) << 4));
        uint4 v = *reinterpret_cast<const uint4*>(smem + soff);
        *reinterpret_cast<uint4*>(gdst + (size_t)u * 16) = v;
    }
}

// ---------------------------------------------------------------------------
// Kernel 2: 32 words per block, 256 threads. Indices staged in smem (u16),
// each warp processes 4 words -> 72 independent table loads in flight.
// smem transpose for coalesced float4 output.
// ---------------------------------------------------------------------------
#define GW 32
__global__ __launch_bounds__(256) void hs_gather_kernel(
    const int* __restrict__ pidx, const float* __restrict__ psign,
    float* __restrict__ out)
{
    __shared__ uint16_t sci[GW * DEPTH];        // 576 packed child indices
    __shared__ float tr[NROWS * (GW + 1)];      // [row][word], pad 33

    const int tid   = threadIdx.x;
    const int lane  = tid & 31;
    const int warp  = tid >> 5;
    const int wbase = blockIdx.x * GW;

    for (int j = tid; j < GW * DEPTH; j += 256) {
        int gj = wbase * DEPTH + j;
        sci[j] = (uint16_t)(2 * pidx[gj] + (psign[gj] < 0.0f ? 1 : 0));
    }
    __syncthreads();

    const __half2* Lp = reinterpret_cast<const __half2*>(g_L);
    float ax[4] = {0.f, 0.f, 0.f, 0.f};
    float ay[4] = {0.f, 0.f, 0.f, 0.f};
#pragma unroll
    for (int d = 0; d < DEPTH; d++) {
#pragma unroll
        for (int j = 0; j < 4; j++) {
            int ci = sci[(warp * 4 + j) * DEPTH + d];
            float2 v = __half22float2(__ldg(&Lp[(size_t)ci * 32 + lane]));
            ax[j] += v.x; ay[j] += v.y;
        }
    }
#pragma unroll
    for (int j = 0; j < 4; j++) {
        tr[(2 * lane)     * (GW + 1) + warp * 4 + j] = ax[j];
        tr[(2 * lane + 1) * (GW + 1) + warp * 4 + j] = ay[j];
    }
    __syncthreads();

#pragma unroll
    for (int i = 0; i < 2; i++) {
        int u   = tid + i * 256;        // float4 unit, 0..511
        int row = u >> 3;
        int wu  = (u & 7) * 4;
        float4 o = make_float4(tr[row * (GW + 1) + wu],     tr[row * (GW + 1) + wu + 1],
                               tr[row * (GW + 1) + wu + 2], tr[row * (GW + 1) + wu + 3]);
        *reinterpret_cast<float4*>(out + (size_t)row * VOCAB + wbase + wu) = o;
    }
}

extern "C" void kernel_launch(void* const* d_in, const int* in_sizes, int n_in,
                              void* d_out, int out_size)
{
    (void)in_sizes; (void)n_in; (void)out_size;
    const float* att   = (const float*)d_in[0];
    const float* W     = (const float*)d_in[1];
    const int*   pidx  = (const int*)d_in[2];
    const float* psign = (const float*)d_in[3];
    float* out = (float*)d_out;

    cudaFuncSetAttribute(hs_gemm_kernel, cudaFuncAttributeMaxDynamicSharedMemorySize, SMEM_TOTAL);
    hs_gemm_kernel<<<(INNER + MT - 1) / MT, 256, SMEM_TOTAL>>>(att, W);
    hs_gather_kernel<<<VOCAB / GW, 256>>>(pidx, psign, out);
}